// round 3
// baseline (speedup 1.0000x reference)
#include <cuda_runtime.h>
#include <math.h>

#define NPART 32768
#define DD 32
#define PP 8
#define HH 128
#define MS 50
#define TPB 128
#define NBLK 128
#define HALFN 16384   // TPB*NBLK; each thread owns 2 particles: t and t+HALFN

typedef unsigned long long u64;

// ---- packed f32x2 helpers (sm_103a) ----
__device__ __forceinline__ u64 pack2(float lo, float hi) {
    u64 r; asm("mov.b64 %0, {%1, %2};" : "=l"(r) : "f"(lo), "f"(hi)); return r;
}
__device__ __forceinline__ void unpack2(u64 v, float& lo, float& hi) {
    asm("mov.b64 {%0, %1}, %2;" : "=f"(lo), "=f"(hi) : "l"(v));
}
__device__ __forceinline__ u64 fma2(u64 a, u64 b, u64 c) {
    u64 d; asm("fma.rn.f32x2 %0, %1, %2, %3;" : "=l"(d) : "l"(a), "l"(b), "l"(c)); return d;
}
__device__ __forceinline__ u64 add2(u64 a, u64 b) {
    u64 d; asm("add.rn.f32x2 %0, %1, %2;" : "=l"(d) : "l"(a), "l"(b)); return d;
}
__device__ __forceinline__ u64 mul2(u64 a, u64 b) {
    u64 d; asm("mul.rn.f32x2 %0, %1, %2;" : "=l"(d) : "l"(a), "l"(b)); return d;
}

__global__ __launch_bounds__(TPB, 1)
void sde_kernel(const float* __restrict__ obs,
                const float* __restrict__ X0,
                const float* __restrict__ V0,
                const float* __restrict__ noise,
                const float* __restrict__ W1,
                const float* __restrict__ b1,
                const float* __restrict__ W2,
                const float* __restrict__ b2,
                const float* __restrict__ theta_p,
                const int*   __restrict__ obsidx_p,
                const int*   __restrict__ cr_p,
                float* __restrict__ outX,
                float* __restrict__ outV)
{
    __shared__ __align__(16) float  W1T[HH][DD];   // W1T[j][i] = W1[i][j]
    __shared__ __align__(16) float  W2s[HH][DD];   // W2s[j][k] = W2[j][k]
    __shared__ float2 cb[HH];                      // (base_j, W1[40][j])
    __shared__ __align__(16) float b2s[DD];

    const int tid = threadIdx.x;

    // ---- stage weights ----
    for (int idx = tid; idx < DD * HH; idx += TPB) {
        int i = idx >> 7;
        int j = idx & (HH - 1);
        W1T[j][i] = W1[idx];
    }
    for (int idx = tid; idx < HH * DD; idx += TPB)
        W2s[idx >> 5][idx & 31] = W2[idx];
    if (tid < DD) b2s[tid] = b2[tid];
    for (int j = tid; j < HH; j += TPB) {
        float base = b1[j];
        #pragma unroll
        for (int q = 0; q < PP; q++)
            base = fmaf(obs[q], W1[(DD + q) * HH + j], base);
        base = fmaf((float)(*obsidx_p), W1[41 * HH + j], base);
        cb[j] = make_float2(base, W1[40 * HH + j]);
    }

    const float theta = *theta_p;
    const float crf   = (float)(*cr_p);
    const float dt    = 0.02f;
    const float sqdt  = sqrtf(dt);

    const u64 sq2   = pack2(sqdt, sqdt);
    const u64 dt2   = pack2(dt, dt);
    const u64 nth2  = pack2(-theta, -theta);
    const u64 ncr2  = pack2(-crf, -crf);
    const u64 zero2 = pack2(0.f, 0.f);

    const int gtid = (int)blockIdx.x * TPB + tid;
    const int pA = gtid;            // particle A
    const int pB = gtid + HALFN;    // particle B
    __syncthreads();

    // ---- state (2 particles), packed f32x2 ----
    u64 XA[DD/2], XB[DD/2], ZA[DD/2], ZB[DD/2];
    {
        const ulonglong2* xa = (const ulonglong2*)(X0 + (size_t)pA * DD);
        const ulonglong2* xb = (const ulonglong2*)(X0 + (size_t)pB * DD);
        #pragma unroll
        for (int i = 0; i < DD/4; i++) {
            ulonglong2 va = xa[i]; XA[2*i] = va.x; XA[2*i+1] = va.y;
            ulonglong2 vb = xb[i]; XB[2*i] = vb.x; XB[2*i+1] = vb.y;
        }
    }
    float VA = V0[pA];
    float VB = V0[pB];

    const u64* b2u = (const u64*)b2s;   // 16 u64

    for (int m = 0; m < MS; m++) {
        const float s = (float)m * dt;

        // prefetch both noise rows (consumed ~4000 cyc later in epilogue)
        u64 NA[DD/2], NB[DD/2];
        {
            const ulonglong2* na =
                (const ulonglong2*)(noise + ((size_t)m * NPART + pA) * DD);
            const ulonglong2* nb =
                (const ulonglong2*)(noise + ((size_t)m * NPART + pB) * DD);
            #pragma unroll
            for (int i = 0; i < DD/4; i++) {
                ulonglong2 va = na[i]; NA[2*i] = va.x; NA[2*i+1] = va.y;
                ulonglong2 vb = nb[i]; NB[2*i] = vb.x; NB[2*i+1] = vb.y;
            }
        }

        #pragma unroll
        for (int i = 0; i < DD/2; i++) { u64 b = b2u[i]; ZA[i] = b; ZB[i] = b; }

        #pragma unroll 2
        for (int j = 0; j < HH; j++) {
            // one set of weight LDS serves BOTH particles
            const ulonglong2* wr = (const ulonglong2*)W1T[j];
            ulonglong2 w0 = wr[0], w1 = wr[1], w2 = wr[2], w3 = wr[3];

            u64 aA0 = zero2, aA1 = zero2, aA2 = zero2, aA3 = zero2;
            u64 aB0 = zero2, aB1 = zero2, aB2 = zero2, aB3 = zero2;

            aA0 = fma2(XA[0], w0.x, aA0);  aB0 = fma2(XB[0], w0.x, aB0);
            aA1 = fma2(XA[1], w0.y, aA1);  aB1 = fma2(XB[1], w0.y, aB1);
            aA2 = fma2(XA[2], w1.x, aA2);  aB2 = fma2(XB[2], w1.x, aB2);
            aA3 = fma2(XA[3], w1.y, aA3);  aB3 = fma2(XB[3], w1.y, aB3);
            aA0 = fma2(XA[4], w2.x, aA0);  aB0 = fma2(XB[4], w2.x, aB0);
            aA1 = fma2(XA[5], w2.y, aA1);  aB1 = fma2(XB[5], w2.y, aB1);
            aA2 = fma2(XA[6], w3.x, aA2);  aB2 = fma2(XB[6], w3.x, aB2);
            aA3 = fma2(XA[7], w3.y, aA3);  aB3 = fma2(XB[7], w3.y, aB3);

            w0 = wr[4]; w1 = wr[5]; w2 = wr[6]; w3 = wr[7];
            aA0 = fma2(XA[8],  w0.x, aA0);  aB0 = fma2(XB[8],  w0.x, aB0);
            aA1 = fma2(XA[9],  w0.y, aA1);  aB1 = fma2(XB[9],  w0.y, aB1);
            aA2 = fma2(XA[10], w1.x, aA2);  aB2 = fma2(XB[10], w1.x, aB2);
            aA3 = fma2(XA[11], w1.y, aA3);  aB3 = fma2(XB[11], w1.y, aB3);
            aA0 = fma2(XA[12], w2.x, aA0);  aB0 = fma2(XB[12], w2.x, aB0);
            aA1 = fma2(XA[13], w2.y, aA1);  aB1 = fma2(XB[13], w2.y, aB1);
            aA2 = fma2(XA[14], w3.x, aA2);  aB2 = fma2(XB[14], w3.x, aB2);
            aA3 = fma2(XA[15], w3.y, aA3);  aB3 = fma2(XB[15], w3.y, aB3);

            aA0 = add2(add2(aA0, aA1), add2(aA2, aA3));
            aB0 = add2(add2(aB0, aB1), add2(aB2, aB3));

            const float2 c = cb[j];
            const float cs = fmaf(s, c.y, c.x);
            float alo, ahi, blo, bhi;
            unpack2(aA0, alo, ahi);
            unpack2(aB0, blo, bhi);
            const float aAv = cs + (alo + ahi);
            const float aBv = cs + (blo + bhi);

            const float eA = __expf(2.0f * aAv);
            const float hA = 1.0f - __fdividef(2.0f, eA + 1.0f);
            const float eB = __expf(2.0f * aBv);
            const float hB = 1.0f - __fdividef(2.0f, eB + 1.0f);
            const u64 hA2 = pack2(hA, hA);
            const u64 hB2 = pack2(hB, hB);

            const ulonglong2* w2r = (const ulonglong2*)W2s[j];
            w0 = w2r[0]; w1 = w2r[1]; w2 = w2r[2]; w3 = w2r[3];
            ZA[0] = fma2(hA2, w0.x, ZA[0]);  ZB[0] = fma2(hB2, w0.x, ZB[0]);
            ZA[1] = fma2(hA2, w0.y, ZA[1]);  ZB[1] = fma2(hB2, w0.y, ZB[1]);
            ZA[2] = fma2(hA2, w1.x, ZA[2]);  ZB[2] = fma2(hB2, w1.x, ZB[2]);
            ZA[3] = fma2(hA2, w1.y, ZA[3]);  ZB[3] = fma2(hB2, w1.y, ZB[3]);
            ZA[4] = fma2(hA2, w2.x, ZA[4]);  ZB[4] = fma2(hB2, w2.x, ZB[4]);
            ZA[5] = fma2(hA2, w2.y, ZA[5]);  ZB[5] = fma2(hB2, w2.y, ZB[5]);
            ZA[6] = fma2(hA2, w3.x, ZA[6]);  ZB[6] = fma2(hB2, w3.x, ZB[6]);
            ZA[7] = fma2(hA2, w3.y, ZA[7]);  ZB[7] = fma2(hB2, w3.y, ZB[7]);
            w0 = w2r[4]; w1 = w2r[5]; w2 = w2r[6]; w3 = w2r[7];
            ZA[8]  = fma2(hA2, w0.x, ZA[8]);   ZB[8]  = fma2(hB2, w0.x, ZB[8]);
            ZA[9]  = fma2(hA2, w0.y, ZA[9]);   ZB[9]  = fma2(hB2, w0.y, ZB[9]);
            ZA[10] = fma2(hA2, w1.x, ZA[10]);  ZB[10] = fma2(hB2, w1.x, ZB[10]);
            ZA[11] = fma2(hA2, w1.y, ZA[11]);  ZB[11] = fma2(hB2, w1.y, ZB[11]);
            ZA[12] = fma2(hA2, w2.x, ZA[12]);  ZB[12] = fma2(hB2, w2.x, ZB[12]);
            ZA[13] = fma2(hA2, w2.y, ZA[13]);  ZB[13] = fma2(hB2, w2.y, ZB[13]);
            ZA[14] = fma2(hA2, w3.x, ZA[14]);  ZB[14] = fma2(hB2, w3.x, ZB[14]);
            ZA[15] = fma2(hA2, w3.y, ZA[15]);  ZB[15] = fma2(hB2, w3.y, ZB[15]);
        }

        // ---- epilogue, one particle at a time (keeps temp regs low) ----
        #pragma unroll
        for (int pp = 0; pp < 2; pp++) {
            u64* Zp = pp ? ZB : ZA;
            u64* Xp = pp ? XB : XA;
            u64* Np = pp ? NB : NA;
            float& V = pp ? VB : VA;

            u64 s20 = zero2, s21 = zero2, s22 = zero2, s23 = zero2;
            u64 zw0 = zero2, zw1 = zero2, zw2 = zero2, zw3 = zero2;
            #pragma unroll
            for (int i = 0; i < 4; i++) {
                u64 za = Zp[4*i],     zb = Zp[4*i + 1];
                u64 zc = Zp[4*i + 2], zd = Zp[4*i + 3];
                s20 = fma2(za, za, s20);
                s21 = fma2(zb, zb, s21);
                s22 = fma2(zc, zc, s22);
                s23 = fma2(zd, zd, s23);
                u64 wa = mul2(sq2, Np[4*i]);
                u64 wb = mul2(sq2, Np[4*i + 1]);
                u64 wc = mul2(sq2, Np[4*i + 2]);
                u64 wd = mul2(sq2, Np[4*i + 3]);
                zw0 = fma2(za, wa, zw0);
                zw1 = fma2(zb, wb, zw1);
                zw2 = fma2(zc, wc, zw2);
                zw3 = fma2(zd, wd, zw3);
                u64 d0 = fma2(ncr2, za, mul2(nth2, Xp[4*i]));
                u64 d1 = fma2(ncr2, zb, mul2(nth2, Xp[4*i + 1]));
                u64 d2 = fma2(ncr2, zc, mul2(nth2, Xp[4*i + 2]));
                u64 d3 = fma2(ncr2, zd, mul2(nth2, Xp[4*i + 3]));
                Xp[4*i]     = add2(fma2(dt2, d0, Xp[4*i]),     wa);
                Xp[4*i + 1] = add2(fma2(dt2, d1, Xp[4*i + 1]), wb);
                Xp[4*i + 2] = add2(fma2(dt2, d2, Xp[4*i + 2]), wc);
                Xp[4*i + 3] = add2(fma2(dt2, d3, Xp[4*i + 3]), wd);
            }
            s20 = add2(add2(s20, s21), add2(s22, s23));
            zw0 = add2(add2(zw0, zw1), add2(zw2, zw3));
            float qlo, qhi, wlo, whi;
            unpack2(s20, qlo, qhi);
            unpack2(zw0, wlo, whi);
            V = fmaf(dt * (0.5f - crf), qlo + qhi, V) + (wlo + whi);
        }
    }

    // ---- store ----
    {
        ulonglong2* xa = (ulonglong2*)(outX + (size_t)pA * DD);
        ulonglong2* xb = (ulonglong2*)(outX + (size_t)pB * DD);
        #pragma unroll
        for (int i = 0; i < DD/4; i++) {
            ulonglong2 va; va.x = XA[2*i]; va.y = XA[2*i+1]; xa[i] = va;
            ulonglong2 vb; vb.x = XB[2*i]; vb.y = XB[2*i+1]; xb[i] = vb;
        }
        outV[pA] = VA;
        outV[pB] = VB;
    }
}

extern "C" void kernel_launch(void* const* d_in, const int* in_sizes, int n_in,
                              void* d_out, int out_size) {
    const float* obs    = (const float*)d_in[0];
    const float* X0     = (const float*)d_in[1];
    const float* V0     = (const float*)d_in[2];
    const float* noise  = (const float*)d_in[3];
    const float* W1     = (const float*)d_in[4];
    const float* b1     = (const float*)d_in[5];
    const float* W2     = (const float*)d_in[6];
    const float* b2     = (const float*)d_in[7];
    const float* theta  = (const float*)d_in[8];
    const int*   obsidx = (const int*)d_in[9];
    const int*   cr     = (const int*)d_in[10];

    float* out  = (float*)d_out;
    float* outX = out;
    float* outV = out + (size_t)NPART * DD;

    sde_kernel<<<NBLK, TPB>>>(obs, X0, V0, noise, W1, b1, W2, b2,
                              theta, obsidx, cr, outX, outV);
}

// round 5
// speedup vs baseline: 1.6190x; 1.6190x over previous
#include <cuda_runtime.h>
#include <math.h>
#include <cstdint>

#define NPART 32768
#define DD 32
#define PP 8
#define HH 128
#define MS 50
#define TPB 128
#define NBLK 148
#define SLOTS (TPB * NBLK)   // 18944 threads; 2 particle slots each

typedef unsigned long long u64;

// ---- packed f32x2 helpers (sm_103a) ----
__device__ __forceinline__ u64 pack2(float lo, float hi) {
    u64 r; asm("mov.b64 %0, {%1, %2};" : "=l"(r) : "f"(lo), "f"(hi)); return r;
}
__device__ __forceinline__ void unpack2(u64 v, float& lo, float& hi) {
    asm("mov.b64 {%0, %1}, %2;" : "=f"(lo), "=f"(hi) : "l"(v));
}
__device__ __forceinline__ u64 fma2(u64 a, u64 b, u64 c) {
    u64 d; asm("fma.rn.f32x2 %0, %1, %2, %3;" : "=l"(d) : "l"(a), "l"(b), "l"(c)); return d;
}
__device__ __forceinline__ u64 add2(u64 a, u64 b) {
    u64 d; asm("add.rn.f32x2 %0, %1, %2;" : "=l"(d) : "l"(a), "l"(b)); return d;
}
__device__ __forceinline__ u64 mul2(u64 a, u64 b) {
    u64 d; asm("mul.rn.f32x2 %0, %1, %2;" : "=l"(d) : "l"(a), "l"(b)); return d;
}
__device__ __forceinline__ uint32_t smem_u32(const void* p) {
    uint32_t a;
    asm("{ .reg .u64 t; cvta.to.shared.u64 t, %1; cvt.u32.u64 %0, t; }"
        : "=r"(a) : "l"(p));
    return a;
}
#define CP16(dst, src) \
    asm volatile("cp.async.cg.shared.global [%0], [%1], 16;" \
                 :: "r"(dst), "l"(src) : "memory")

// shared layout (float offsets)
#define F_W1T 0                      // [j][i] 128x32
#define F_W2S (F_W1T + HH * DD)      // [j][k] 128x32
#define F_CB  (F_W2S + HH * DD)      // float2[128]
#define F_B2  (F_CB + 2 * HH)        // 32
#define F_NA  (F_B2 + DD)            // noise staging A: [chunk(8)][tid(128)][4]
#define F_NB  (F_NA + TPB * DD)
#define SMEM_FLOATS (F_NB + TPB * DD)
#define SMEM_BYTES (SMEM_FLOATS * 4)

__global__ __launch_bounds__(TPB, 1)
void sde_kernel(const float* __restrict__ obs,
                const float* __restrict__ X0,
                const float* __restrict__ V0,
                const float* __restrict__ noise,
                const float* __restrict__ W1,
                const float* __restrict__ b1,
                const float* __restrict__ W2,
                const float* __restrict__ b2,
                const float* __restrict__ theta_p,
                const int*   __restrict__ obsidx_p,
                const int*   __restrict__ cr_p,
                float* __restrict__ outX,
                float* __restrict__ outV)
{
    extern __shared__ __align__(16) float sm[];
    float*  W1T = sm + F_W1T;
    float*  W2s = sm + F_W2S;
    float2* cb  = (float2*)(sm + F_CB);
    float*  b2s = sm + F_B2;
    float*  nsA = sm + F_NA;
    float*  nsB = sm + F_NB;

    const int tid = threadIdx.x;

    // ---- stage weights ----
    for (int idx = tid; idx < DD * HH; idx += TPB) {
        int i = idx >> 7;            // feature
        int j = idx & (HH - 1);      // hidden unit
        W1T[j * DD + i] = W1[idx];
    }
    for (int idx = tid; idx < HH * DD; idx += TPB)
        W2s[idx] = W2[idx];          // already [j][k]
    if (tid < DD) b2s[tid] = b2[tid];
    {
        const int j = tid;           // TPB == HH
        float base = b1[j];
        #pragma unroll
        for (int q = 0; q < PP; q++)
            base = fmaf(obs[q], W1[(DD + q) * HH + j], base);
        base = fmaf((float)(*obsidx_p), W1[41 * HH + j], base);
        cb[j] = make_float2(base, W1[40 * HH + j]);
    }

    const float theta = *theta_p;
    const float crf   = (float)(*cr_p);
    const float dt    = 0.02f;
    const float sqdt  = sqrtf(dt);

    const u64 sq2   = pack2(sqdt, sqdt);
    const u64 dt2   = pack2(dt, dt);
    const u64 nth2  = pack2(-theta, -theta);
    const u64 ncr2  = pack2(-crf, -crf);
    const u64 zero2 = pack2(0.f, 0.f);

    const int gtid = (int)blockIdx.x * TPB + tid;
    const int pA  = gtid;
    const int pB  = gtid + SLOTS;
    const int pBc = (pB < NPART) ? pB : (NPART - 1);   // clamp for loads

    const uint32_t nsAu = smem_u32(nsA) + (uint32_t)tid * 16u;
    const uint32_t nsBu = smem_u32(nsB) + (uint32_t)tid * 16u;
    const float* nArd = nsA + tid * 4;
    const float* nBrd = nsB + tid * 4;

    __syncthreads();

    // ---- state (2 particles) packed f32x2 ----
    u64 XA[DD/2], XB[DD/2], ZA[DD/2], ZB[DD/2];
    {
        const ulonglong2* xa = (const ulonglong2*)(X0 + (size_t)pA * DD);
        const ulonglong2* xb = (const ulonglong2*)(X0 + (size_t)pBc * DD);
        #pragma unroll
        for (int i = 0; i < DD/4; i++) {
            ulonglong2 va = xa[i]; XA[2*i] = va.x; XA[2*i+1] = va.y;
            ulonglong2 vb = xb[i]; XB[2*i] = vb.x; XB[2*i+1] = vb.y;
        }
    }
    float VA = V0[pA];
    float VB = V0[pBc];

    const u64* b2u = (const u64*)b2s;

    for (int m = 0; m < MS; m++) {
        const float s = (float)m * dt;

        // stage this step's noise rows into shared (consumed at epilogue)
        {
            const float* srcA = noise + ((size_t)m * NPART + pA) * DD;
            const float* srcB = noise + ((size_t)m * NPART + pBc) * DD;
            #pragma unroll
            for (int i = 0; i < 8; i++) {
                CP16(nsAu + (uint32_t)i * (TPB * 16u), srcA + i * 4);
                CP16(nsBu + (uint32_t)i * (TPB * 16u), srcB + i * 4);
            }
            asm volatile("cp.async.commit_group;" ::: "memory");
        }

        #pragma unroll
        for (int i = 0; i < DD/2; i++) { u64 b = b2u[i]; ZA[i] = b; ZB[i] = b; }

        #pragma unroll 2
        for (int j = 0; j < HH; j++) {
            const ulonglong2* wr = (const ulonglong2*)(W1T + j * DD);
            ulonglong2 w0 = wr[0], w1 = wr[1], w2 = wr[2], w3 = wr[3];

            u64 aA0 = zero2, aA1 = zero2, aA2 = zero2, aA3 = zero2;
            u64 aB0 = zero2, aB1 = zero2, aB2 = zero2, aB3 = zero2;

            aA0 = fma2(XA[0], w0.x, aA0);  aB0 = fma2(XB[0], w0.x, aB0);
            aA1 = fma2(XA[1], w0.y, aA1);  aB1 = fma2(XB[1], w0.y, aB1);
            aA2 = fma2(XA[2], w1.x, aA2);  aB2 = fma2(XB[2], w1.x, aB2);
            aA3 = fma2(XA[3], w1.y, aA3);  aB3 = fma2(XB[3], w1.y, aB3);
            aA0 = fma2(XA[4], w2.x, aA0);  aB0 = fma2(XB[4], w2.x, aB0);
            aA1 = fma2(XA[5], w2.y, aA1);  aB1 = fma2(XB[5], w2.y, aB1);
            aA2 = fma2(XA[6], w3.x, aA2);  aB2 = fma2(XB[6], w3.x, aB2);
            aA3 = fma2(XA[7], w3.y, aA3);  aB3 = fma2(XB[7], w3.y, aB3);

            w0 = wr[4]; w1 = wr[5]; w2 = wr[6]; w3 = wr[7];
            aA0 = fma2(XA[8],  w0.x, aA0);  aB0 = fma2(XB[8],  w0.x, aB0);
            aA1 = fma2(XA[9],  w0.y, aA1);  aB1 = fma2(XB[9],  w0.y, aB1);
            aA2 = fma2(XA[10], w1.x, aA2);  aB2 = fma2(XB[10], w1.x, aB2);
            aA3 = fma2(XA[11], w1.y, aA3);  aB3 = fma2(XB[11], w1.y, aB3);
            aA0 = fma2(XA[12], w2.x, aA0);  aB0 = fma2(XB[12], w2.x, aB0);
            aA1 = fma2(XA[13], w2.y, aA1);  aB1 = fma2(XB[13], w2.y, aB1);
            aA2 = fma2(XA[14], w3.x, aA2);  aB2 = fma2(XB[14], w3.x, aB2);
            aA3 = fma2(XA[15], w3.y, aA3);  aB3 = fma2(XB[15], w3.y, aB3);

            aA0 = add2(add2(aA0, aA1), add2(aA2, aA3));
            aB0 = add2(add2(aB0, aB1), add2(aB2, aB3));

            const float2 c = cb[j];
            const float cs = fmaf(s, c.y, c.x);
            float alo, ahi, blo, bhi;
            unpack2(aA0, alo, ahi);
            unpack2(aB0, blo, bhi);
            const float aAv = cs + (alo + ahi);
            const float aBv = cs + (blo + bhi);

            const float eA = __expf(2.0f * aAv);
            const float hA = 1.0f - __fdividef(2.0f, eA + 1.0f);
            const float eB = __expf(2.0f * aBv);
            const float hB = 1.0f - __fdividef(2.0f, eB + 1.0f);
            const u64 hA2 = pack2(hA, hA);
            const u64 hB2 = pack2(hB, hB);

            const ulonglong2* w2r = (const ulonglong2*)(W2s + j * DD);
            w0 = w2r[0]; w1 = w2r[1]; w2 = w2r[2]; w3 = w2r[3];
            ZA[0] = fma2(hA2, w0.x, ZA[0]);  ZB[0] = fma2(hB2, w0.x, ZB[0]);
            ZA[1] = fma2(hA2, w0.y, ZA[1]);  ZB[1] = fma2(hB2, w0.y, ZB[1]);
            ZA[2] = fma2(hA2, w1.x, ZA[2]);  ZB[2] = fma2(hB2, w1.x, ZB[2]);
            ZA[3] = fma2(hA2, w1.y, ZA[3]);  ZB[3] = fma2(hB2, w1.y, ZB[3]);
            ZA[4] = fma2(hA2, w2.x, ZA[4]);  ZB[4] = fma2(hB2, w2.x, ZB[4]);
            ZA[5] = fma2(hA2, w2.y, ZA[5]);  ZB[5] = fma2(hB2, w2.y, ZB[5]);
            ZA[6] = fma2(hA2, w3.x, ZA[6]);  ZB[6] = fma2(hB2, w3.x, ZB[6]);
            ZA[7] = fma2(hA2, w3.y, ZA[7]);  ZB[7] = fma2(hB2, w3.y, ZB[7]);
            w0 = w2r[4]; w1 = w2r[5]; w2 = w2r[6]; w3 = w2r[7];
            ZA[8]  = fma2(hA2, w0.x, ZA[8]);   ZB[8]  = fma2(hB2, w0.x, ZB[8]);
            ZA[9]  = fma2(hA2, w0.y, ZA[9]);   ZB[9]  = fma2(hB2, w0.y, ZB[9]);
            ZA[10] = fma2(hA2, w1.x, ZA[10]);  ZB[10] = fma2(hB2, w1.x, ZB[10]);
            ZA[11] = fma2(hA2, w1.y, ZA[11]);  ZB[11] = fma2(hB2, w1.y, ZB[11]);
            ZA[12] = fma2(hA2, w2.x, ZA[12]);  ZB[12] = fma2(hB2, w2.x, ZB[12]);
            ZA[13] = fma2(hA2, w2.y, ZA[13]);  ZB[13] = fma2(hB2, w2.y, ZB[13]);
            ZA[14] = fma2(hA2, w3.x, ZA[14]);  ZB[14] = fma2(hB2, w3.x, ZB[14]);
            ZA[15] = fma2(hA2, w3.y, ZA[15]);  ZB[15] = fma2(hB2, w3.y, ZB[15]);
        }

        // ---- epilogue (noise from shared; per particle) ----
        asm volatile("cp.async.wait_group 0;" ::: "memory");

        #pragma unroll
        for (int pp = 0; pp < 2; pp++) {
            u64* Zp = pp ? ZB : ZA;
            u64* Xp = pp ? XB : XA;
            const float* nrd = pp ? nBrd : nArd;
            float& V = pp ? VB : VA;

            u64 s20 = zero2, s21 = zero2, s22 = zero2, s23 = zero2;
            u64 zw0 = zero2, zw1 = zero2, zw2 = zero2, zw3 = zero2;
            #pragma unroll
            for (int i = 0; i < 4; i++) {
                // chunks 2i, 2i+1 -> 4 packed noise values
                ulonglong2 nv0 = *(const ulonglong2*)(nrd + (2*i)     * (TPB * 4));
                ulonglong2 nv1 = *(const ulonglong2*)(nrd + (2*i + 1) * (TPB * 4));
                u64 za = Zp[4*i],     zb = Zp[4*i + 1];
                u64 zc = Zp[4*i + 2], zd = Zp[4*i + 3];
                s20 = fma2(za, za, s20);
                s21 = fma2(zb, zb, s21);
                s22 = fma2(zc, zc, s22);
                s23 = fma2(zd, zd, s23);
                u64 wa = mul2(sq2, nv0.x);
                u64 wb = mul2(sq2, nv0.y);
                u64 wc = mul2(sq2, nv1.x);
                u64 wd = mul2(sq2, nv1.y);
                zw0 = fma2(za, wa, zw0);
                zw1 = fma2(zb, wb, zw1);
                zw2 = fma2(zc, wc, zw2);
                zw3 = fma2(zd, wd, zw3);
                u64 d0 = fma2(ncr2, za, mul2(nth2, Xp[4*i]));
                u64 d1 = fma2(ncr2, zb, mul2(nth2, Xp[4*i + 1]));
                u64 d2 = fma2(ncr2, zc, mul2(nth2, Xp[4*i + 2]));
                u64 d3 = fma2(ncr2, zd, mul2(nth2, Xp[4*i + 3]));
                Xp[4*i]     = add2(fma2(dt2, d0, Xp[4*i]),     wa);
                Xp[4*i + 1] = add2(fma2(dt2, d1, Xp[4*i + 1]), wb);
                Xp[4*i + 2] = add2(fma2(dt2, d2, Xp[4*i + 2]), wc);
                Xp[4*i + 3] = add2(fma2(dt2, d3, Xp[4*i + 3]), wd);
            }
            s20 = add2(add2(s20, s21), add2(s22, s23));
            zw0 = add2(add2(zw0, zw1), add2(zw2, zw3));
            float qlo, qhi, wlo, whi;
            unpack2(s20, qlo, qhi);
            unpack2(zw0, wlo, whi);
            V = fmaf(dt * (0.5f - crf), qlo + qhi, V) + (wlo + whi);
        }
    }

    // ---- store ----
    {
        ulonglong2* xa = (ulonglong2*)(outX + (size_t)pA * DD);
        #pragma unroll
        for (int i = 0; i < DD/4; i++) {
            ulonglong2 va; va.x = XA[2*i]; va.y = XA[2*i+1]; xa[i] = va;
        }
        outV[pA] = VA;
        if (pB < NPART) {
            ulonglong2* xb = (ulonglong2*)(outX + (size_t)pB * DD);
            #pragma unroll
            for (int i = 0; i < DD/4; i++) {
                ulonglong2 vb; vb.x = XB[2*i]; vb.y = XB[2*i+1]; xb[i] = vb;
            }
            outV[pB] = VB;
        }
    }
}

extern "C" void kernel_launch(void* const* d_in, const int* in_sizes, int n_in,
                              void* d_out, int out_size) {
    const float* obs    = (const float*)d_in[0];
    const float* X0     = (const float*)d_in[1];
    const float* V0     = (const float*)d_in[2];
    const float* noise  = (const float*)d_in[3];
    const float* W1     = (const float*)d_in[4];
    const float* b1     = (const float*)d_in[5];
    const float* W2     = (const float*)d_in[6];
    const float* b2     = (const float*)d_in[7];
    const float* theta  = (const float*)d_in[8];
    const int*   obsidx = (const int*)d_in[9];
    const int*   cr     = (const int*)d_in[10];

    float* out  = (float*)d_out;
    float* outX = out;
    float* outV = out + (size_t)NPART * DD;

    cudaFuncSetAttribute(sde_kernel,
                         cudaFuncAttributeMaxDynamicSharedMemorySize, SMEM_BYTES);
    sde_kernel<<<NBLK, TPB, SMEM_BYTES>>>(obs, X0, V0, noise, W1, b1, W2, b2,
                                          theta, obsidx, cr, outX, outV);
}